// round 10
// baseline (speedup 1.0000x reference)
#include <cuda_runtime.h>
#include <cuda_fp16.h>
#include <cstdint>

// Problem constants (fixed by the reference config)
#define SEQ   512
#define BATCH 64
#define NN    1024
#define SIN   64
#define NT    512          // threads per block (2 neurons / thread)
#define NWARP (NT/32)      // 16
#define ROWU  (NN/2)       // 512 uints (2 halves each) per weight row
#define ZOFFU (NN*(NN/2))  // uint offset of the implicit zero row (bss-zeroed)

// Transposed fp16 weights + one trailing zero row each (zero-initialized bss).
__device__ __half g_W1H[NN * NN + NN];
__device__ __half g_W2H[NN * NN + NN];

// ---------------------------------------------------------------------------
// Tiled transpose+convert of both 1024x1024 fp32 matrices to fp16.
// ---------------------------------------------------------------------------
__global__ void transpose_both(const float* __restrict__ W1in,
                               const float* __restrict__ W2in) {
    __shared__ float tile[32][33];
    const float* in  = blockIdx.z ? W2in : W1in;
    __half*      out = blockIdx.z ? g_W2H : g_W1H;
    int bx = blockIdx.x * 32, by = blockIdx.y * 32;
    int tx = threadIdx.x, ty = threadIdx.y;
#pragma unroll
    for (int j = 0; j < 32; j += 8)
        tile[ty + j][tx] = in[(size_t)(by + ty + j) * NN + (bx + tx)];
    __syncthreads();
#pragma unroll
    for (int j = 0; j < 32; j += 8)
        out[(size_t)(bx + ty + j) * NN + (by + tx)] = __float2half(tile[tx][ty + j]);
}

// ---------------------------------------------------------------------------
// Gather-accumulate fp16 rows W[off[s] + tid], s in [0, numPad), numPad % 16
// == 0, no predication (padding entries point at the zero row). Chunks of 16
// independent LDG.32 (16-reg buffer) before any convert/add.
// ---------------------------------------------------------------------------
__device__ __forceinline__ float2 gather_h(const unsigned* __restrict__ W,
                                           const int* __restrict__ off,
                                           int numPad, int tid)
{
    float2 acc = make_float2(0.f, 0.f);
    for (int c = 0; c < numPad; c += 16) {
        unsigned w[16];
#pragma unroll
        for (int j = 0; j < 16; j++)
            w[j] = W[off[c + j] + tid];
        float2 p0 = make_float2(0.f, 0.f), p1 = p0, p2 = p0, p3 = p0;
#pragma unroll
        for (int j = 0; j < 16; j += 4) {
            float2 a0 = __half22float2(*reinterpret_cast<__half2*>(&w[j+0]));
            p0.x += a0.x; p0.y += a0.y;
            float2 a1 = __half22float2(*reinterpret_cast<__half2*>(&w[j+1]));
            p1.x += a1.x; p1.y += a1.y;
            float2 a2 = __half22float2(*reinterpret_cast<__half2*>(&w[j+2]));
            p2.x += a2.x; p2.y += a2.y;
            float2 a3 = __half22float2(*reinterpret_cast<__half2*>(&w[j+3]));
            p3.x += a3.x; p3.y += a3.y;
        }
        acc.x += (p0.x + p1.x) + (p2.x + p3.x);
        acc.y += (p0.y + p1.y) + (p2.y + p3.y);
    }
    return acc;
}

// ---------------------------------------------------------------------------
// Persistent LIF kernel: one CTA per batch element, loops over all SEQ steps.
// Thread t owns neurons {2t, 2t+1} of BOTH layers (float2 state in registers).
// 16 warps/CTA for latency hiding; input ids double-buffered + prefetched.
// ---------------------------------------------------------------------------
__global__ __launch_bounds__(NT, 1)
void lif_persistent(const float* __restrict__ decay1, const float* __restrict__ decay2,
                    const float* __restrict__ th1,    const float* __restrict__ th2,
                    const float* __restrict__ v1init, const float* __restrict__ v2init,
                    const int*   __restrict__ spk_ids, const int* __restrict__ spk_num,
                    float* __restrict__ out)
{
    const int b    = blockIdx.x;
    const int tid  = threadIdx.x;
    const int lane = tid & 31;
    const int warp = tid >> 5;

    // Output sections (reference tuple order, all fp32)
    float* out_ids1 = out;
    float* out_ids2 = out + (size_t)SEQ * BATCH * SIN;
    float* out_cnt1 = out + (size_t)2 * SEQ * BATCH * SIN;
    float* out_cnt2 = out_cnt1 + (size_t)SEQ * BATCH * 2;
    float* out_st1  = out_cnt2 + (size_t)SEQ * BATCH * 2;
    float* out_st2  = out_st1  + (size_t)SEQ * BATCH * NN;

    float2 v1 = ((const float2*)v1init)[b * (NN/2) + tid];
    float2 v2 = ((const float2*)v2init)[b * (NN/2) + tid];
    const float2 d1 = ((const float2*)decay1)[tid];
    const float2 d2 = ((const float2*)decay2)[tid];
    const float2 t1 = ((const float2*)th1)[tid];
    const float2 t2 = ((const float2*)th2)[tid];
    const float2 od1 = make_float2(1.f - d1.x, 1.f - d1.y);
    const float2 od2 = make_float2(1.f - d2.x, 1.f - d2.y);
    const float2 h1  = make_float2(0.9f * t1.x, 0.9f * t1.y);
    const float2 h2  = make_float2(0.9f * t2.x, 0.9f * t2.y);

    __shared__ int s_ids[2][SIN];     // double-buffered uint row offsets, zero-padded
    __shared__ int s_num[2];
    __shared__ int s_spk[NN];         // layer-1 spiking ids (ascending)
    __shared__ int s_spkoff[NN + 16]; // same, pre-scaled + zero-row padding
    __shared__ int s_ns[SIN];         // layer-1 non-spiking padding ids
    __shared__ int s_spk2[SIN];
    __shared__ int s_ns2[SIN];
    __shared__ int s_wsum[NWARP];
    __shared__ int s_tot;

    const unsigned* __restrict__ W1 = (const unsigned*)g_W1H;
    const unsigned* __restrict__ W2 = (const unsigned*)g_W2H;

    // ---- prologue: stage step-0 inputs (padded with zero-row offsets) ----
    if (tid < SIN) {
        int n0num = spk_num[b];                       // uniform broadcast load
        int id    = spk_ids[(size_t)b * SIN + tid];
        s_ids[0][tid] = (tid < n0num) ? id * ROWU : ZOFFU;
        if (tid == 0) s_num[0] = n0num;
    }
    __syncthreads();

    for (int t = 0; t < SEQ; t++) {
        const int buf = t & 1;

        // ---- prefetch step t+1 staging data (latency hidden under the step) ----
        int nid = 0, nnum = 0;
        {
            int tn = (t + 1 < SEQ) ? t + 1 : t;       // clamped; unused at t=SEQ-1
            if (tid < SIN) {
                nnum = spk_num[tn * BATCH + b];       // uniform broadcast load
                nid  = spk_ids[((size_t)tn * BATCH + b) * SIN + tid];
            }
        }

        // ---- layer 1: sparse gather-accumulate (fp16 rows, no predication) ----
        const int num    = s_num[buf];
        const int numPad = (num + 15) & ~15;
        float2 acc = gather_h(W1, s_ids[buf], numPad, tid);

        v1.x = d1.x * v1.x + od1.x * acc.x;
        v1.y = d1.y * v1.y + od1.y * acc.y;
        const bool p0 = v1.x > t1.x, p1 = v1.y > t1.y;
        int c  = (int)p0 + (int)p1;
        int c2 = (int)(v1.x > h1.x) + (int)(v1.y > h1.y);

        // ---- packed scan: low16 = spike count, high16 = second count ----
        int packed = c | (c2 << 16);
        int incl = packed;
#pragma unroll
        for (int o = 1; o < 32; o <<= 1) {
            int y = __shfl_up_sync(0xffffffffu, incl, o);
            if (lane >= o) incl += y;
        }
        if (lane == 31) s_wsum[warp] = incl;
        __syncthreads();
        if (warp == 0) {
            int v = (lane < NWARP) ? s_wsum[lane] : 0;
            int e = v;
#pragma unroll
            for (int o = 1; o < NWARP; o <<= 1) {
                int y = __shfl_up_sync(0xffffffffu, e, o);
                if (lane >= o) e += y;
            }
            if (lane < NWARP) s_wsum[lane] = e - v;   // exclusive
            if (lane == NWARP - 1) s_tot = e;
        }
        __syncthreads();
        int gp          = (s_wsum[warp] + (incl - packed)) & 0xffff;
        const int tot   = s_tot;
        const int c1tot = tot & 0xffff;
        const int c2tot = tot >> 16;

        // ---- emit compacted lists (+ zero-row padding), reset, state trace ----
        const int n0 = tid * 2;
        if (p0) { s_spk[gp] = n0;     s_spkoff[gp] = n0 * ROWU;       gp++; }
        else    { int np = n0 - gp;       if (np < SIN) s_ns[np] = n0; }
        if (p1) { s_spk[gp] = n0 + 1; s_spkoff[gp] = (n0 + 1) * ROWU; gp++; }
        else    { int np = (n0 + 1) - gp; if (np < SIN) s_ns[np] = n0 + 1; }
        if (tid < 16) s_spkoff[c1tot + tid] = ZOFFU;  // disjoint from emit range
        if (p0) v1.x = 0.0f;
        if (p1) v1.y = 0.0f;
        __stcs(&((float2*)out_st1)[((size_t)t * BATCH + b) * (NN/2) + tid], v1);
        __syncthreads();

        if (tid < SIN) {
            int id = (tid < c1tot) ? s_spk[tid] : s_ns[tid - c1tot];
            out_ids1[((size_t)t * BATCH + b) * SIN + tid] = (float)id;
        }
        if (tid < 2)
            out_cnt1[((size_t)t * BATCH + b) * 2 + tid] = (float)(tid == 0 ? c1tot : c2tot);

        // ---- layer 2: gather W2 rows of spiking layer-1 neurons ----
        const int numPad2 = (c1tot + 15) & ~15;
        float2 acc2 = gather_h(W2, s_spkoff, numPad2, tid);

        v2.x = d2.x * v2.x + od2.x * acc2.x;
        v2.y = d2.y * v2.y + od2.y * acc2.y;
        const bool q0 = v2.x > t2.x, q1 = v2.y > t2.y;
        c  = (int)q0 + (int)q1;
        c2 = (int)(v2.x > h2.x) + (int)(v2.y > h2.y);

        packed = c | (c2 << 16);
        incl = packed;
#pragma unroll
        for (int o = 1; o < 32; o <<= 1) {
            int y = __shfl_up_sync(0xffffffffu, incl, o);
            if (lane >= o) incl += y;
        }
        if (lane == 31) s_wsum[warp] = incl;
        __syncthreads();
        if (warp == 0) {
            int v = (lane < NWARP) ? s_wsum[lane] : 0;
            int e = v;
#pragma unroll
            for (int o = 1; o < NWARP; o <<= 1) {
                int y = __shfl_up_sync(0xffffffffu, e, o);
                if (lane >= o) e += y;
            }
            if (lane < NWARP) s_wsum[lane] = e - v;
            if (lane == NWARP - 1) s_tot = e;
        }
        __syncthreads();
        int gq           = (s_wsum[warp] + (incl - packed)) & 0xffff;
        const int tot2   = s_tot;
        const int c1tot2 = tot2 & 0xffff;
        const int c2tot2 = tot2 >> 16;

        if (q0) { if (gq < SIN) s_spk2[gq] = n0;     gq++; }
        else    { int np = n0 - gq;       if (np < SIN) s_ns2[np] = n0; }
        if (q1) { if (gq < SIN) s_spk2[gq] = n0 + 1; gq++; }
        else    { int np = (n0 + 1) - gq; if (np < SIN) s_ns2[np] = n0 + 1; }
        if (q0) v2.x = 0.0f;
        if (q1) v2.y = 0.0f;
        __stcs(&((float2*)out_st2)[((size_t)t * BATCH + b) * (NN/2) + tid], v2);

        // ---- commit prefetched staging data (padded) to the alternate buffer ----
        if (tid < SIN) {
            s_ids[buf ^ 1][tid] = (tid < nnum) ? nid * ROWU : ZOFFU;
            if (tid == 0) s_num[buf ^ 1] = nnum;
        }
        __syncthreads();   // protects s_spk2/s_ns2 reads below AND next-step staging

        if (tid < SIN) {
            int id = (tid < c1tot2) ? s_spk2[tid] : s_ns2[tid - c1tot2];
            out_ids2[((size_t)t * BATCH + b) * SIN + tid] = (float)id;
        }
        if (tid < 2)
            out_cnt2[((size_t)t * BATCH + b) * 2 + tid] = (float)(tid == 0 ? c1tot2 : c2tot2);
    }
}

// ---------------------------------------------------------------------------
extern "C" void kernel_launch(void* const* d_in, const int* in_sizes, int n_in,
                              void* d_out, int out_size) {
    const float* W1     = (const float*)d_in[0];
    const float* W2     = (const float*)d_in[1];
    const float* decay1 = (const float*)d_in[2];
    const float* decay2 = (const float*)d_in[3];
    const float* th1    = (const float*)d_in[4];
    const float* th2    = (const float*)d_in[5];
    const float* v1init = (const float*)d_in[6];
    const float* v2init = (const float*)d_in[7];
    const int*   spkids = (const int*)d_in[8];
    const int*   spknum = (const int*)d_in[9];
    float* out = (float*)d_out;

    dim3 tb(32, 8), tg(32, 32, 2);
    transpose_both<<<tg, tb>>>(W1, W2);
    lif_persistent<<<BATCH, NT>>>(decay1, decay2, th1, th2,
                                  v1init, v2init, spkids, spknum, out);
}

// round 11
// speedup vs baseline: 1.5766x; 1.5766x over previous
#include <cuda_runtime.h>
#include <cuda_fp16.h>
#include <cstdint>

// Problem constants (fixed by the reference config)
#define SEQ   512
#define BATCH 64
#define NN    1024
#define SIN   64
#define NT    256          // lif threads per block (4 neurons / thread)
#define NWARP (NT/32)      // 8
#define ROW2  (NN/4)       // 256 uint2 (4 halves each) per weight/I1 row
#define ZOFF2 (NN*(NN/4))  // uint2 offset of the implicit zero row (bss-zeroed)

// Transposed fp16 weights + one trailing zero row each (zero-initialized bss).
__device__ __half g_W1H[NN * NN + NN];
__device__ __half g_W2H[NN * NN + NN];
// Precomputed layer-1 input currents I1[t][b][n], fp16.
__device__ __half g_I1[(size_t)SEQ * BATCH * NN];

// ---------------------------------------------------------------------------
// Tiled transpose+convert of both 1024x1024 fp32 matrices to fp16.
// ---------------------------------------------------------------------------
__global__ void transpose_both(const float* __restrict__ W1in,
                               const float* __restrict__ W2in) {
    __shared__ float tile[32][33];
    const float* in  = blockIdx.z ? W2in : W1in;
    __half*      out = blockIdx.z ? g_W2H : g_W1H;
    int bx = blockIdx.x * 32, by = blockIdx.y * 32;
    int tx = threadIdx.x, ty = threadIdx.y;
#pragma unroll
    for (int j = 0; j < 32; j += 8)
        tile[ty + j][tx] = in[(size_t)(by + ty + j) * NN + (bx + tx)];
    __syncthreads();
#pragma unroll
    for (int j = 0; j < 32; j += 8)
        out[(size_t)(bx + ty + j) * NN + (by + tx)] = __float2half(tile[tx][ty + j]);
}

// ---------------------------------------------------------------------------
// Gather-accumulate fp16 rows W[off[s] + tid], s in [0, numPad), numPad % 16
// == 0, no predication (padding entries point at the zero row). Chunks of 16
// independent LDG.64 before any convert/add.
// ---------------------------------------------------------------------------
__device__ __forceinline__ float4 gather_h2(const uint2* __restrict__ W,
                                            const int* __restrict__ off,
                                            int numPad, int tid)
{
    float4 acc = make_float4(0.f, 0.f, 0.f, 0.f);
    for (int c = 0; c < numPad; c += 16) {
        uint2 w[16];
#pragma unroll
        for (int j = 0; j < 16; j++)
            w[j] = W[off[c + j] + tid];
        float4 p0 = make_float4(0.f,0.f,0.f,0.f), p1 = p0, p2 = p0, p3 = p0;
#pragma unroll
        for (int j = 0; j < 16; j += 4) {
            float2 a0 = __half22float2(*reinterpret_cast<__half2*>(&w[j+0].x));
            float2 b0 = __half22float2(*reinterpret_cast<__half2*>(&w[j+0].y));
            p0.x += a0.x; p0.y += a0.y; p0.z += b0.x; p0.w += b0.y;
            float2 a1 = __half22float2(*reinterpret_cast<__half2*>(&w[j+1].x));
            float2 b1 = __half22float2(*reinterpret_cast<__half2*>(&w[j+1].y));
            p1.x += a1.x; p1.y += a1.y; p1.z += b1.x; p1.w += b1.y;
            float2 a2 = __half22float2(*reinterpret_cast<__half2*>(&w[j+2].x));
            float2 b2 = __half22float2(*reinterpret_cast<__half2*>(&w[j+2].y));
            p2.x += a2.x; p2.y += a2.y; p2.z += b2.x; p2.w += b2.y;
            float2 a3 = __half22float2(*reinterpret_cast<__half2*>(&w[j+3].x));
            float2 b3 = __half22float2(*reinterpret_cast<__half2*>(&w[j+3].y));
            p3.x += a3.x; p3.y += a3.y; p3.z += b3.x; p3.w += b3.y;
        }
        acc.x += (p0.x + p1.x) + (p2.x + p3.x);
        acc.y += (p0.y + p1.y) + (p2.y + p3.y);
        acc.z += (p0.z + p1.z) + (p2.z + p3.z);
        acc.w += (p0.w + p1.w) + (p2.w + p3.w);
    }
    return acc;
}

// ---------------------------------------------------------------------------
// Massively parallel precompute of I1: one CTA per (t, b) pair. The layer-1
// input current is independent of the recurrent state, so all SEQ*BATCH
// gathers run concurrently on all SMs (throughput-bound on L2-resident W1).
// ---------------------------------------------------------------------------
__global__ __launch_bounds__(NT)
void precompute_I1(const int* __restrict__ spk_ids, const int* __restrict__ spk_num) {
    const int tb  = blockIdx.x;          // t * BATCH + b
    const int tid = threadIdx.x;
    __shared__ int s_off[SIN];
    __shared__ int s_np;
    if (tid < SIN) {
        int num = spk_num[tb];           // uniform broadcast load
        int id  = spk_ids[(size_t)tb * SIN + tid];
        s_off[tid] = (tid < num) ? id * ROW2 : ZOFF2;
        if (tid == 0) s_np = (num + 15) & ~15;
    }
    __syncthreads();
    float4 acc = gather_h2((const uint2*)g_W1H, s_off, s_np, tid);
    __half2 h01 = __floats2half2_rn(acc.x, acc.y);
    __half2 h23 = __floats2half2_rn(acc.z, acc.w);
    uint2 o;
    o.x = *reinterpret_cast<unsigned*>(&h01);
    o.y = *reinterpret_cast<unsigned*>(&h23);
    ((uint2*)g_I1)[(size_t)tb * ROW2 + tid] = o;
}

// ---------------------------------------------------------------------------
// Persistent LIF kernel: one CTA per batch element, loops over all SEQ steps.
// Thread t owns neurons {4t..4t+3} of BOTH layers (float4 state in registers).
// Layer-1 input current comes from the precomputed g_I1 (one prefetched
// LDG.64 per thread per step) — no layer-1 gather in the serial loop.
// ---------------------------------------------------------------------------
__global__ __launch_bounds__(NT, 1)
void lif_persistent(const float* __restrict__ decay1, const float* __restrict__ decay2,
                    const float* __restrict__ th1,    const float* __restrict__ th2,
                    const float* __restrict__ v1init, const float* __restrict__ v2init,
                    float* __restrict__ out)
{
    const int b    = blockIdx.x;
    const int tid  = threadIdx.x;
    const int lane = tid & 31;
    const int warp = tid >> 5;

    // Output sections (reference tuple order, all fp32)
    float* out_ids1 = out;
    float* out_ids2 = out + (size_t)SEQ * BATCH * SIN;
    float* out_cnt1 = out + (size_t)2 * SEQ * BATCH * SIN;
    float* out_cnt2 = out_cnt1 + (size_t)SEQ * BATCH * 2;
    float* out_st1  = out_cnt2 + (size_t)SEQ * BATCH * 2;
    float* out_st2  = out_st1  + (size_t)SEQ * BATCH * NN;

    float4 v1 = ((const float4*)v1init)[b * (NN/4) + tid];
    float4 v2 = ((const float4*)v2init)[b * (NN/4) + tid];
    const float4 d1 = ((const float4*)decay1)[tid];
    const float4 d2 = ((const float4*)decay2)[tid];
    const float4 t1 = ((const float4*)th1)[tid];
    const float4 t2 = ((const float4*)th2)[tid];
    const float4 od1 = make_float4(1.f - d1.x, 1.f - d1.y, 1.f - d1.z, 1.f - d1.w);
    const float4 od2 = make_float4(1.f - d2.x, 1.f - d2.y, 1.f - d2.z, 1.f - d2.w);
    const float4 h1 = make_float4(0.9f*t1.x, 0.9f*t1.y, 0.9f*t1.z, 0.9f*t1.w);
    const float4 h2 = make_float4(0.9f*t2.x, 0.9f*t2.y, 0.9f*t2.z, 0.9f*t2.w);

    __shared__ int s_spk[NN];         // layer-1 spiking ids (ascending)
    __shared__ int s_spkoff[NN + 16]; // same, pre-scaled + zero-row padding
    __shared__ int s_ns[SIN];         // layer-1 non-spiking padding ids
    __shared__ int s_spk2[SIN];
    __shared__ int s_ns2[SIN];
    __shared__ int s_wsum[NWARP];
    __shared__ int s_tot;

    const uint2* __restrict__ I1 = (const uint2*)g_I1;
    const uint2* __restrict__ W2 = (const uint2*)g_W2H;

    // ---- prologue: fetch step-0 I1 row ----
    uint2 cur = I1[(size_t)b * ROW2 + tid];

    for (int t = 0; t < SEQ; t++) {
        // ---- prefetch step t+1 I1 row (latency hidden under the step) ----
        int tn = (t + 1 < SEQ) ? t + 1 : t;           // clamped; unused at t=SEQ-1
        uint2 nxt = I1[((size_t)tn * BATCH + b) * ROW2 + tid];

        // ---- layer 1: membrane update from precomputed current ----
        float2 a01 = __half22float2(*reinterpret_cast<__half2*>(&cur.x));
        float2 a23 = __half22float2(*reinterpret_cast<__half2*>(&cur.y));
        v1.x = d1.x * v1.x + od1.x * a01.x;
        v1.y = d1.y * v1.y + od1.y * a01.y;
        v1.z = d1.z * v1.z + od1.z * a23.x;
        v1.w = d1.w * v1.w + od1.w * a23.y;
        const bool p0 = v1.x > t1.x, p1 = v1.y > t1.y,
                   p2 = v1.z > t1.z, p3 = v1.w > t1.w;
        int c  = (int)p0 + (int)p1 + (int)p2 + (int)p3;
        int c2 = (int)(v1.x > h1.x) + (int)(v1.y > h1.y)
               + (int)(v1.z > h1.z) + (int)(v1.w > h1.w);

        // ---- packed scan: low16 = spike count, high16 = second count ----
        int packed = c | (c2 << 16);
        int incl = packed;
#pragma unroll
        for (int o = 1; o < 32; o <<= 1) {
            int y = __shfl_up_sync(0xffffffffu, incl, o);
            if (lane >= o) incl += y;
        }
        if (lane == 31) s_wsum[warp] = incl;
        __syncthreads();
        if (warp == 0) {
            int v = (lane < NWARP) ? s_wsum[lane] : 0;
            int e = v;
#pragma unroll
            for (int o = 1; o < NWARP; o <<= 1) {
                int y = __shfl_up_sync(0xffffffffu, e, o);
                if (lane >= o) e += y;
            }
            if (lane < NWARP) s_wsum[lane] = e - v;   // exclusive
            if (lane == NWARP - 1) s_tot = e;
        }
        __syncthreads();
        int gp          = (s_wsum[warp] + (incl - packed)) & 0xffff;
        const int tot   = s_tot;
        const int c1tot = tot & 0xffff;
        const int c2tot = tot >> 16;

        // ---- emit compacted lists (+ zero-row padding), reset, state trace ----
        const int n0 = tid * 4;
        const bool pr[4] = {p0, p1, p2, p3};
#pragma unroll
        for (int k = 0; k < 4; k++) {
            int id = n0 + k;
            if (pr[k]) { s_spk[gp] = id; s_spkoff[gp] = id * ROW2; gp++; }
            else       { int np = id - gp; if (np < SIN) s_ns[np] = id; }
        }
        if (tid < 16) s_spkoff[c1tot + tid] = ZOFF2;  // disjoint from emit range
        if (p0) v1.x = 0.0f;
        if (p1) v1.y = 0.0f;
        if (p2) v1.z = 0.0f;
        if (p3) v1.w = 0.0f;
        __stcs(&((float4*)out_st1)[((size_t)t * BATCH + b) * (NN/4) + tid], v1);
        __syncthreads();

        if (tid < SIN) {
            int id = (tid < c1tot) ? s_spk[tid] : s_ns[tid - c1tot];
            out_ids1[((size_t)t * BATCH + b) * SIN + tid] = (float)id;
        }
        if (tid < 2)
            out_cnt1[((size_t)t * BATCH + b) * 2 + tid] = (float)(tid == 0 ? c1tot : c2tot);

        // ---- layer 2: gather W2 rows of spiking layer-1 neurons (usually 0) ----
        const int numPad2 = (c1tot + 15) & ~15;
        float4 acc2 = gather_h2(W2, s_spkoff, numPad2, tid);

        v2.x = d2.x * v2.x + od2.x * acc2.x;
        v2.y = d2.y * v2.y + od2.y * acc2.y;
        v2.z = d2.z * v2.z + od2.z * acc2.z;
        v2.w = d2.w * v2.w + od2.w * acc2.w;
        const bool q0 = v2.x > t2.x, q1 = v2.y > t2.y,
                   q2 = v2.z > t2.z, q3 = v2.w > t2.w;
        c  = (int)q0 + (int)q1 + (int)q2 + (int)q3;
        c2 = (int)(v2.x > h2.x) + (int)(v2.y > h2.y)
           + (int)(v2.z > h2.z) + (int)(v2.w > h2.w);

        packed = c | (c2 << 16);
        incl = packed;
#pragma unroll
        for (int o = 1; o < 32; o <<= 1) {
            int y = __shfl_up_sync(0xffffffffu, incl, o);
            if (lane >= o) incl += y;
        }
        if (lane == 31) s_wsum[warp] = incl;
        __syncthreads();
        if (warp == 0) {
            int v = (lane < NWARP) ? s_wsum[lane] : 0;
            int e = v;
#pragma unroll
            for (int o = 1; o < NWARP; o <<= 1) {
                int y = __shfl_up_sync(0xffffffffu, e, o);
                if (lane >= o) e += y;
            }
            if (lane < NWARP) s_wsum[lane] = e - v;
            if (lane == NWARP - 1) s_tot = e;
        }
        __syncthreads();
        int gq           = (s_wsum[warp] + (incl - packed)) & 0xffff;
        const int tot2   = s_tot;
        const int c1tot2 = tot2 & 0xffff;
        const int c2tot2 = tot2 >> 16;

        const bool qr[4] = {q0, q1, q2, q3};
#pragma unroll
        for (int k = 0; k < 4; k++) {
            int id = n0 + k;
            if (qr[k]) { if (gq < SIN) s_spk2[gq] = id; gq++; }
            else       { int np = id - gq; if (np < SIN) s_ns2[np] = id; }
        }
        if (q0) v2.x = 0.0f;
        if (q1) v2.y = 0.0f;
        if (q2) v2.z = 0.0f;
        if (q3) v2.w = 0.0f;
        __stcs(&((float4*)out_st2)[((size_t)t * BATCH + b) * (NN/4) + tid], v2);
        __syncthreads();   // protects s_spk2/s_ns2 reads below

        if (tid < SIN) {
            int id = (tid < c1tot2) ? s_spk2[tid] : s_ns2[tid - c1tot2];
            out_ids2[((size_t)t * BATCH + b) * SIN + tid] = (float)id;
        }
        if (tid < 2)
            out_cnt2[((size_t)t * BATCH + b) * 2 + tid] = (float)(tid == 0 ? c1tot2 : c2tot2);

        cur = nxt;
    }
}

// ---------------------------------------------------------------------------
extern "C" void kernel_launch(void* const* d_in, const int* in_sizes, int n_in,
                              void* d_out, int out_size) {
    const float* W1     = (const float*)d_in[0];
    const float* W2     = (const float*)d_in[1];
    const float* decay1 = (const float*)d_in[2];
    const float* decay2 = (const float*)d_in[3];
    const float* th1    = (const float*)d_in[4];
    const float* th2    = (const float*)d_in[5];
    const float* v1init = (const float*)d_in[6];
    const float* v2init = (const float*)d_in[7];
    const int*   spkids = (const int*)d_in[8];
    const int*   spknum = (const int*)d_in[9];
    float* out = (float*)d_out;

    dim3 tb(32, 8), tg(32, 32, 2);
    transpose_both<<<tg, tb>>>(W1, W2);
    precompute_I1<<<SEQ * BATCH, NT>>>(spkids, spknum);
    lif_persistent<<<BATCH, NT>>>(decay1, decay2, th1, th2,
                                  v1init, v2init, out);
}

// round 12
// speedup vs baseline: 2.1405x; 1.3577x over previous
#include <cuda_runtime.h>
#include <cuda_fp16.h>
#include <cstdint>

// Problem constants (fixed by the reference config)
#define SEQ   512
#define BATCH 64
#define NN    1024
#define SIN   64
#define NT    256          // lif threads per block (4 neurons / thread)
#define NWARP (NT/32)      // 8
#define ROW2  (NN/4)       // 256 uint2 (4 halves each) per weight/I1 row
#define ZOFF2 (NN*(NN/4))  // uint2 offset of the implicit zero row (bss-zeroed)

// Transposed fp16 weights + one trailing zero row each (zero-initialized bss).
__device__ __half g_W1H[NN * NN + NN];
__device__ __half g_W2H[NN * NN + NN];
// Precomputed layer-1 input currents I1[t][b][n], fp16.
__device__ __half g_I1[(size_t)SEQ * BATCH * NN];

// ---------------------------------------------------------------------------
// Tiled transpose+convert of both 1024x1024 fp32 matrices to fp16.
// ---------------------------------------------------------------------------
__global__ void transpose_both(const float* __restrict__ W1in,
                               const float* __restrict__ W2in) {
    __shared__ float tile[32][33];
    const float* in  = blockIdx.z ? W2in : W1in;
    __half*      out = blockIdx.z ? g_W2H : g_W1H;
    int bx = blockIdx.x * 32, by = blockIdx.y * 32;
    int tx = threadIdx.x, ty = threadIdx.y;
#pragma unroll
    for (int j = 0; j < 32; j += 8)
        tile[ty + j][tx] = in[(size_t)(by + ty + j) * NN + (bx + tx)];
    __syncthreads();
#pragma unroll
    for (int j = 0; j < 32; j += 8)
        out[(size_t)(bx + ty + j) * NN + (by + tx)] = __float2half(tile[tx][ty + j]);
}

// ---------------------------------------------------------------------------
// Gather-accumulate fp16 rows W[off[s] + tid], s in [0, numPad), numPad % 16
// == 0, no predication (padding entries point at the zero row). Chunks of 16
// independent LDG.64 before any convert/add.
// ---------------------------------------------------------------------------
__device__ __forceinline__ float4 gather_h2(const uint2* __restrict__ W,
                                            const int* __restrict__ off,
                                            int numPad, int tid)
{
    float4 acc = make_float4(0.f, 0.f, 0.f, 0.f);
    for (int c = 0; c < numPad; c += 16) {
        uint2 w[16];
#pragma unroll
        for (int j = 0; j < 16; j++)
            w[j] = W[off[c + j] + tid];
        float4 p0 = make_float4(0.f,0.f,0.f,0.f), p1 = p0, p2 = p0, p3 = p0;
#pragma unroll
        for (int j = 0; j < 16; j += 4) {
            float2 a0 = __half22float2(*reinterpret_cast<__half2*>(&w[j+0].x));
            float2 b0 = __half22float2(*reinterpret_cast<__half2*>(&w[j+0].y));
            p0.x += a0.x; p0.y += a0.y; p0.z += b0.x; p0.w += b0.y;
            float2 a1 = __half22float2(*reinterpret_cast<__half2*>(&w[j+1].x));
            float2 b1 = __half22float2(*reinterpret_cast<__half2*>(&w[j+1].y));
            p1.x += a1.x; p1.y += a1.y; p1.z += b1.x; p1.w += b1.y;
            float2 a2 = __half22float2(*reinterpret_cast<__half2*>(&w[j+2].x));
            float2 b2 = __half22float2(*reinterpret_cast<__half2*>(&w[j+2].y));
            p2.x += a2.x; p2.y += a2.y; p2.z += b2.x; p2.w += b2.y;
            float2 a3 = __half22float2(*reinterpret_cast<__half2*>(&w[j+3].x));
            float2 b3 = __half22float2(*reinterpret_cast<__half2*>(&w[j+3].y));
            p3.x += a3.x; p3.y += a3.y; p3.z += b3.x; p3.w += b3.y;
        }
        acc.x += (p0.x + p1.x) + (p2.x + p3.x);
        acc.y += (p0.y + p1.y) + (p2.y + p3.y);
        acc.z += (p0.z + p1.z) + (p2.z + p3.z);
        acc.w += (p0.w + p1.w) + (p2.w + p3.w);
    }
    return acc;
}

// ---------------------------------------------------------------------------
// Massively parallel precompute of I1: one CTA per (t, b) pair.
// ---------------------------------------------------------------------------
__global__ __launch_bounds__(NT)
void precompute_I1(const int* __restrict__ spk_ids, const int* __restrict__ spk_num) {
    const int tb  = blockIdx.x;          // t * BATCH + b
    const int tid = threadIdx.x;
    __shared__ int s_off[SIN];
    __shared__ int s_np;
    if (tid < SIN) {
        int num = spk_num[tb];           // uniform broadcast load
        int id  = spk_ids[(size_t)tb * SIN + tid];
        s_off[tid] = (tid < num) ? id * ROW2 : ZOFF2;
        if (tid == 0) s_np = (num + 15) & ~15;
    }
    __syncthreads();
    float4 acc = gather_h2((const uint2*)g_W1H, s_off, s_np, tid);
    __half2 h01 = __floats2half2_rn(acc.x, acc.y);
    __half2 h23 = __floats2half2_rn(acc.z, acc.w);
    uint2 o;
    o.x = *reinterpret_cast<unsigned*>(&h01);
    o.y = *reinterpret_cast<unsigned*>(&h23);
    ((uint2*)g_I1)[(size_t)tb * ROW2 + tid] = o;
}

// ---------------------------------------------------------------------------
// Persistent LIF kernel: one CTA per batch element, loops over all SEQ steps.
// Fast path: when __syncthreads_or says no neuron crossed either threshold,
// outputs are closed-form (ids = iota, cnt = 0, no resets, no layer-2 input)
// and the step needs only 2 barriers and zero smem traffic. Slow path keeps
// the exact scan/compaction for the general case (branch is block-uniform).
// ---------------------------------------------------------------------------
__global__ __launch_bounds__(NT, 1)
void lif_persistent(const float* __restrict__ decay1, const float* __restrict__ decay2,
                    const float* __restrict__ th1,    const float* __restrict__ th2,
                    const float* __restrict__ v1init, const float* __restrict__ v2init,
                    float* __restrict__ out)
{
    const int b    = blockIdx.x;
    const int tid  = threadIdx.x;
    const int lane = tid & 31;
    const int warp = tid >> 5;

    // Output sections (reference tuple order, all fp32)
    float* out_ids1 = out;
    float* out_ids2 = out + (size_t)SEQ * BATCH * SIN;
    float* out_cnt1 = out + (size_t)2 * SEQ * BATCH * SIN;
    float* out_cnt2 = out_cnt1 + (size_t)SEQ * BATCH * 2;
    float* out_st1  = out_cnt2 + (size_t)SEQ * BATCH * 2;
    float* out_st2  = out_st1  + (size_t)SEQ * BATCH * NN;

    float4 v1 = ((const float4*)v1init)[b * (NN/4) + tid];
    float4 v2 = ((const float4*)v2init)[b * (NN/4) + tid];
    const float4 d1 = ((const float4*)decay1)[tid];
    const float4 d2 = ((const float4*)decay2)[tid];
    const float4 t1 = ((const float4*)th1)[tid];
    const float4 t2 = ((const float4*)th2)[tid];
    const float4 od1 = make_float4(1.f - d1.x, 1.f - d1.y, 1.f - d1.z, 1.f - d1.w);
    const float4 od2 = make_float4(1.f - d2.x, 1.f - d2.y, 1.f - d2.z, 1.f - d2.w);
    const float4 h1 = make_float4(0.9f*t1.x, 0.9f*t1.y, 0.9f*t1.z, 0.9f*t1.w);
    const float4 h2 = make_float4(0.9f*t2.x, 0.9f*t2.y, 0.9f*t2.z, 0.9f*t2.w);
    const float ftid = (float)tid;       // fast-path iota id

    __shared__ int s_spk[NN];         // layer-1 spiking ids (ascending)
    __shared__ int s_spkoff[NN + 16]; // same, pre-scaled + zero-row padding
    __shared__ int s_ns[SIN];         // layer-1 non-spiking padding ids
    __shared__ int s_spk2[SIN];
    __shared__ int s_ns2[SIN];
    __shared__ int s_wsum[NWARP];
    __shared__ int s_tot;

    const uint2* __restrict__ I1 = (const uint2*)g_I1;
    const uint2* __restrict__ W2 = (const uint2*)g_W2H;

    // ---- prologue: fetch step-0 I1 row ----
    uint2 cur = I1[(size_t)b * ROW2 + tid];

    for (int t = 0; t < SEQ; t++) {
        // ---- prefetch step t+1 I1 row (latency hidden under the step) ----
        int tn = (t + 1 < SEQ) ? t + 1 : t;           // clamped; unused at t=SEQ-1
        uint2 nxt = I1[((size_t)tn * BATCH + b) * ROW2 + tid];

        // ---- layer 1: membrane update from precomputed current ----
        float2 a01 = __half22float2(*reinterpret_cast<__half2*>(&cur.x));
        float2 a23 = __half22float2(*reinterpret_cast<__half2*>(&cur.y));
        v1.x = d1.x * v1.x + od1.x * a01.x;
        v1.y = d1.y * v1.y + od1.y * a01.y;
        v1.z = d1.z * v1.z + od1.z * a23.x;
        v1.w = d1.w * v1.w + od1.w * a23.y;
        const bool p0 = v1.x > t1.x, p1 = v1.y > t1.y,
                   p2 = v1.z > t1.z, p3 = v1.w > t1.w;
        int c  = (int)p0 + (int)p1 + (int)p2 + (int)p3;
        int c2 = (int)(v1.x > h1.x) + (int)(v1.y > h1.y)
               + (int)(v1.z > h1.z) + (int)(v1.w > h1.w);
        int packed = c | (c2 << 16);

        const size_t tbIdx = (size_t)t * BATCH + b;
        int c1tot = 0;

        // ---- one BAR.RED decides fast vs exact-compaction path ----
        if (__syncthreads_or(packed) == 0) {
            // no spike, no second-threshold cross anywhere in the CTA
            if (tid < SIN) out_ids1[tbIdx * SIN + tid] = ftid;
            if (tid < 2)   out_cnt1[tbIdx * 2 + tid]   = 0.0f;
            __stcs(&((float4*)out_st1)[tbIdx * (NN/4) + tid], v1);
        } else {
            // ---- exact scan/compaction (rare) ----
            int incl = packed;
#pragma unroll
            for (int o = 1; o < 32; o <<= 1) {
                int y = __shfl_up_sync(0xffffffffu, incl, o);
                if (lane >= o) incl += y;
            }
            if (lane == 31) s_wsum[warp] = incl;
            __syncthreads();
            if (warp == 0) {
                int v = (lane < NWARP) ? s_wsum[lane] : 0;
                int e = v;
#pragma unroll
                for (int o = 1; o < NWARP; o <<= 1) {
                    int y = __shfl_up_sync(0xffffffffu, e, o);
                    if (lane >= o) e += y;
                }
                if (lane < NWARP) s_wsum[lane] = e - v;   // exclusive
                if (lane == NWARP - 1) s_tot = e;
            }
            __syncthreads();
            int gp        = (s_wsum[warp] + (incl - packed)) & 0xffff;
            const int tot = s_tot;
            c1tot         = tot & 0xffff;
            const int c2tot = tot >> 16;

            const int n0 = tid * 4;
            const bool pr[4] = {p0, p1, p2, p3};
#pragma unroll
            for (int k = 0; k < 4; k++) {
                int id = n0 + k;
                if (pr[k]) { s_spk[gp] = id; s_spkoff[gp] = id * ROW2; gp++; }
                else       { int np = id - gp; if (np < SIN) s_ns[np] = id; }
            }
            if (tid < 16) s_spkoff[c1tot + tid] = ZOFF2;
            if (p0) v1.x = 0.0f;
            if (p1) v1.y = 0.0f;
            if (p2) v1.z = 0.0f;
            if (p3) v1.w = 0.0f;
            __stcs(&((float4*)out_st1)[tbIdx * (NN/4) + tid], v1);
            __syncthreads();

            if (tid < SIN) {
                int id = (tid < c1tot) ? s_spk[tid] : s_ns[tid - c1tot];
                out_ids1[tbIdx * SIN + tid] = (float)id;
            }
            if (tid < 2)
                out_cnt1[tbIdx * 2 + tid] = (float)(tid == 0 ? c1tot : c2tot);
        }

        // ---- layer 2: input only if layer 1 spiked ----
        float4 acc2 = make_float4(0.f, 0.f, 0.f, 0.f);
        if (c1tot > 0)
            acc2 = gather_h2(W2, s_spkoff, (c1tot + 15) & ~15, tid);

        v2.x = d2.x * v2.x + od2.x * acc2.x;
        v2.y = d2.y * v2.y + od2.y * acc2.y;
        v2.z = d2.z * v2.z + od2.z * acc2.z;
        v2.w = d2.w * v2.w + od2.w * acc2.w;
        const bool q0 = v2.x > t2.x, q1 = v2.y > t2.y,
                   q2 = v2.z > t2.z, q3 = v2.w > t2.w;
        c  = (int)q0 + (int)q1 + (int)q2 + (int)q3;
        c2 = (int)(v2.x > h2.x) + (int)(v2.y > h2.y)
           + (int)(v2.z > h2.z) + (int)(v2.w > h2.w);
        packed = c | (c2 << 16);

        if (__syncthreads_or(packed) == 0) {
            if (tid < SIN) out_ids2[tbIdx * SIN + tid] = ftid;
            if (tid < 2)   out_cnt2[tbIdx * 2 + tid]   = 0.0f;
            __stcs(&((float4*)out_st2)[tbIdx * (NN/4) + tid], v2);
        } else {
            int incl = packed;
#pragma unroll
            for (int o = 1; o < 32; o <<= 1) {
                int y = __shfl_up_sync(0xffffffffu, incl, o);
                if (lane >= o) incl += y;
            }
            if (lane == 31) s_wsum[warp] = incl;
            __syncthreads();
            if (warp == 0) {
                int v = (lane < NWARP) ? s_wsum[lane] : 0;
                int e = v;
#pragma unroll
                for (int o = 1; o < NWARP; o <<= 1) {
                    int y = __shfl_up_sync(0xffffffffu, e, o);
                    if (lane >= o) e += y;
                }
                if (lane < NWARP) s_wsum[lane] = e - v;
                if (lane == NWARP - 1) s_tot = e;
            }
            __syncthreads();
            int gq           = (s_wsum[warp] + (incl - packed)) & 0xffff;
            const int tot2   = s_tot;
            const int c1tot2 = tot2 & 0xffff;
            const int c2tot2 = tot2 >> 16;

            const int n0 = tid * 4;
            const bool qr[4] = {q0, q1, q2, q3};
#pragma unroll
            for (int k = 0; k < 4; k++) {
                int id = n0 + k;
                if (qr[k]) { if (gq < SIN) s_spk2[gq] = id; gq++; }
                else       { int np = id - gq; if (np < SIN) s_ns2[np] = id; }
            }
            if (q0) v2.x = 0.0f;
            if (q1) v2.y = 0.0f;
            if (q2) v2.z = 0.0f;
            if (q3) v2.w = 0.0f;
            __stcs(&((float4*)out_st2)[tbIdx * (NN/4) + tid], v2);
            __syncthreads();

            if (tid < SIN) {
                int id = (tid < c1tot2) ? s_spk2[tid] : s_ns2[tid - c1tot2];
                out_ids2[tbIdx * SIN + tid] = (float)id;
            }
            if (tid < 2)
                out_cnt2[tbIdx * 2 + tid] = (float)(tid == 0 ? c1tot2 : c2tot2);
        }

        cur = nxt;
    }
}

// ---------------------------------------------------------------------------
extern "C" void kernel_launch(void* const* d_in, const int* in_sizes, int n_in,
                              void* d_out, int out_size) {
    const float* W1     = (const float*)d_in[0];
    const float* W2     = (const float*)d_in[1];
    const float* decay1 = (const float*)d_in[2];
    const float* decay2 = (const float*)d_in[3];
    const float* th1    = (const float*)d_in[4];
    const float* th2    = (const float*)d_in[5];
    const float* v1init = (const float*)d_in[6];
    const float* v2init = (const float*)d_in[7];
    const int*   spkids = (const int*)d_in[8];
    const int*   spknum = (const int*)d_in[9];
    float* out = (float*)d_out;

    dim3 tb(32, 8), tg(32, 32, 2);
    transpose_both<<<tg, tb>>>(W1, W2);
    precompute_I1<<<SEQ * BATCH, NT>>>(spkids, spknum);
    lif_persistent<<<BATCH, NT>>>(decay1, decay2, th1, th2,
                                  v1init, v2init, out);
}